// round 7
// baseline (speedup 1.0000x reference)
#include <cuda_runtime.h>

#define NN 100000
#define EE 1600000
#define HALF_E 800000
#define HH 64

// Scratch (device globals; no allocation allowed)
__device__ float g_h[NN * HH];
__device__ float g_agg[NN * HH];

__device__ __forceinline__ float frelu(float x) { return x > 0.f ? x : 0.f; }

typedef unsigned long long ull;

// ---- packed f32x2 helpers (FFMA2 — only reachable via PTX) -----------------
__device__ __forceinline__ ull pk2(float lo, float hi) {
    ull r;
    asm("mov.b64 %0, {%1,%2};" : "=l"(r) : "f"(lo), "f"(hi));
    return r;
}
__device__ __forceinline__ void upk2(ull v, float& lo, float& hi) {
    asm("mov.b64 {%0,%1}, %2;" : "=f"(lo), "=f"(hi) : "l"(v));
}
__device__ __forceinline__ ull ffma2(ull a, ull b, ull c) {
    ull d;
    asm("fma.rn.f32x2 %0, %1, %2, %3;" : "=l"(d) : "l"(a), "l"(b), "l"(c));
    return d;
}

// ---------------------------------------------------------------------------
// Edge kernel: msg = relu(h[src] + edge_attr); agg[dst] += msg
// 8 lanes/edge (R3 mapping, empirically best), 2 edges/thread (e, e+HALF_E)
// with all wide loads front-batched for 2x memory-level parallelism.
// __ldcs on the edge_attr stream so it doesn't evict L2-resident h / agg.
// ---------------------------------------------------------------------------
__global__ void __launch_bounds__(256) edge_kernel(
    const float4* __restrict__ h,
    const float4* __restrict__ ea,
    const int* __restrict__ src,
    const int* __restrict__ dst,
    float4* __restrict__ agg)
{
    int t = blockIdx.x * 256 + threadIdx.x;
    int e0 = t >> 3;                 // 0 .. HALF_E-1 (grid sized exactly)
    int c = t & 7;
    int e1 = e0 + HALF_E;

    int s0 = __ldg(&src[e0]);
    int d0 = __ldg(&dst[e0]);
    int s1 = __ldg(&src[e1]);
    int d1 = __ldg(&dst[e1]);

    float4 a0 = __ldcs(&ea[(size_t)e0 * 16 + c]);
    float4 a1 = __ldcs(&ea[(size_t)e0 * 16 + c + 8]);
    float4 a2 = __ldcs(&ea[(size_t)e1 * 16 + c]);
    float4 a3 = __ldcs(&ea[(size_t)e1 * 16 + c + 8]);

    float4 h0 = __ldg(&h[(size_t)s0 * 16 + c]);
    float4 h1 = __ldg(&h[(size_t)s0 * 16 + c + 8]);
    float4 h2 = __ldg(&h[(size_t)s1 * 16 + c]);
    float4 h3 = __ldg(&h[(size_t)s1 * 16 + c + 8]);

    float4 m0, m1, m2, m3;
    m0.x = frelu(a0.x + h0.x); m0.y = frelu(a0.y + h0.y);
    m0.z = frelu(a0.z + h0.z); m0.w = frelu(a0.w + h0.w);
    m1.x = frelu(a1.x + h1.x); m1.y = frelu(a1.y + h1.y);
    m1.z = frelu(a1.z + h1.z); m1.w = frelu(a1.w + h1.w);
    m2.x = frelu(a2.x + h2.x); m2.y = frelu(a2.y + h2.y);
    m2.z = frelu(a2.z + h2.z); m2.w = frelu(a2.w + h2.w);
    m3.x = frelu(a3.x + h3.x); m3.y = frelu(a3.y + h3.y);
    m3.z = frelu(a3.z + h3.z); m3.w = frelu(a3.w + h3.w);

    atomicAdd(&agg[(size_t)d0 * 16 + c], m0);
    atomicAdd(&agg[(size_t)d0 * 16 + c + 8], m1);
    atomicAdd(&agg[(size_t)d1 * 16 + c], m2);
    atomicAdd(&agg[(size_t)d1 * 16 + c + 8], m3);
}

// ---------------------------------------------------------------------------
// Conv MLP kernel (R5 shape + pre-packed weights):
// out = relu_opt(relu(in@W1+b1)@W2+b2) + resid
// 256 threads = 8 warps, 64 nodes/block, 8 nodes/warp. Packed (even-k, odd-k)
// accumulators; horizontal add at the end. Weights staged PRE-PACKED as
// (W[2kp][l], W[2kp+1][l]) ull pairs -> 2 LDS.64 per k-pair (no movs).
// ---------------------------------------------------------------------------
#define MLP_SMEM_FLOATS (4096 + 4096 + 64 + 64 + 64 * 64)
__global__ void __launch_bounds__(256) mlp_kernel(
    const float* __restrict__ in,
    const float* __restrict__ resid,
    const float* __restrict__ W1, const float* __restrict__ b1,
    const float* __restrict__ W2, const float* __restrict__ b2,
    float* __restrict__ out1, float* __restrict__ out2,
    int relu_out)
{
    extern __shared__ float sm[];
    ull*   sW1p = (ull*)sm;              // 2048 ull: [kp][l] packed pairs
    ull*   sW2p = (ull*)(sm + 4096);     // 2048 ull
    float* sb1  = sm + 8192;             // 64
    float* sb2  = sm + 8256;             // 64
    float* sIn  = sm + 8320;             // [node][64]

    const int tid = threadIdx.x;
    const int base = blockIdx.x * 64;

    for (int i = tid; i < 2048; i += 256) {
        int kp = i >> 6, lc = i & 63;
        sW1p[i] = pk2(W1[(2 * kp) * 64 + lc], W1[(2 * kp + 1) * 64 + lc]);
        sW2p[i] = pk2(W2[(2 * kp) * 64 + lc], W2[(2 * kp + 1) * 64 + lc]);
    }
    if (tid < 64) { sb1[tid] = b1[tid]; sb2[tid] = b2[tid]; }
    for (int i = tid; i < 64 * 16; i += 256) {
        int nd = i >> 4, c = i & 15;
        float4 v = make_float4(0.f, 0.f, 0.f, 0.f);
        if (base + nd < NN) v = ((const float4*)in)[(size_t)(base + nd) * 16 + c];
        ((float4*)(sIn + nd * 64))[c] = v;
    }
    __syncthreads();

    const int w = tid >> 5, l = tid & 31;
    const int ln0 = w * 8;

    ull acc0[8], acc1[8];
    {
        ull bb0 = pk2(sb1[l], 0.f);
        ull bb1 = pk2(sb1[l + 32], 0.f);
#pragma unroll
        for (int j = 0; j < 8; j++) { acc0[j] = bb0; acc1[j] = bb1; }
    }

#pragma unroll 8
    for (int kp = 0; kp < 32; kp++) {
        ull w0p = sW1p[kp * 64 + l];
        ull w1p = sW1p[kp * 64 + l + 32];
#pragma unroll
        for (int j = 0; j < 8; j++) {
            ull vp = *(const ull*)&sIn[(ln0 + j) * 64 + 2 * kp];
            acc0[j] = ffma2(vp, w0p, acc0[j]);
            acc1[j] = ffma2(vp, w1p, acc1[j]);
        }
    }

    __syncwarp();
#pragma unroll
    for (int j = 0; j < 8; j++) {
        float x0, x1, y0, y1;
        upk2(acc0[j], x0, x1);
        upk2(acc1[j], y0, y1);
        sIn[(ln0 + j) * 64 + l]      = frelu(x0 + x1);
        sIn[(ln0 + j) * 64 + l + 32] = frelu(y0 + y1);
    }
    __syncwarp();

    {
        ull bb0 = pk2(sb2[l], 0.f);
        ull bb1 = pk2(sb2[l + 32], 0.f);
#pragma unroll
        for (int j = 0; j < 8; j++) { acc0[j] = bb0; acc1[j] = bb1; }
    }

#pragma unroll 8
    for (int kp = 0; kp < 32; kp++) {
        ull w0p = sW2p[kp * 64 + l];
        ull w1p = sW2p[kp * 64 + l + 32];
#pragma unroll
        for (int j = 0; j < 8; j++) {
            ull vp = *(const ull*)&sIn[(ln0 + j) * 64 + 2 * kp];
            acc0[j] = ffma2(vp, w0p, acc0[j]);
            acc1[j] = ffma2(vp, w1p, acc1[j]);
        }
    }

#pragma unroll
    for (int j = 0; j < 8; j++) {
        int nd = base + ln0 + j;
        if (nd < NN) {
            float x0, x1, y0, y1;
            upk2(acc0[j], x0, x1);
            upk2(acc1[j], y0, y1);
            float v0 = x0 + x1, v1 = y0 + y1;
            if (relu_out) { v0 = frelu(v0); v1 = frelu(v1); }
            v0 += resid[(size_t)nd * 64 + l];
            v1 += resid[(size_t)nd * 64 + l + 32];
            out1[(size_t)nd * 64 + l] = v0;
            out1[(size_t)nd * 64 + l + 32] = v1;
            if (out2) { out2[(size_t)nd * 64 + l] = v0; out2[(size_t)nd * 64 + l + 32] = v1; }
        }
    }
}

// ---------------------------------------------------------------------------
// Init kernel (FFMA2, k-packed): h0 = relu(concat(emb[z],t)@rw1+rb1)@rw2+rb2
// Input dim 65: emb in [nd][0..63] (stride 68), t at [nd][64]. Writes h0 to
// both g_h and g_agg.
// ---------------------------------------------------------------------------
#define INIT_SMEM_FLOATS (65 * 64 + 4096 + 64 + 64 + 64 * 68)
__global__ void __launch_bounds__(256) init_kernel(
    const int* __restrict__ z,
    const float* __restrict__ t,
    const float* __restrict__ emb,
    const float* __restrict__ W1, const float* __restrict__ b1,
    const float* __restrict__ W2, const float* __restrict__ b2,
    float* __restrict__ out1, float* __restrict__ out2)
{
    extern __shared__ float sm[];
    float* sW1 = sm;                    // 65*64 = 4160
    float* sW2 = sm + 4160;             // 64*64
    float* sb1 = sm + 8256;             // 64
    float* sb2 = sm + 8320;             // 64
    float* sIn = sm + 8384;             // [node][68] (65 used)
    __shared__ int sZ[64];

    const int tid = threadIdx.x;
    const int base = blockIdx.x * 64;

    for (int i = tid; i < 4160; i += 256) sW1[i] = W1[i];
    for (int i = tid; i < 4096; i += 256) sW2[i] = W2[i];
    if (tid < 64) {
        sb1[tid] = b1[tid]; sb2[tid] = b2[tid];
        int nd = base + tid;
        sZ[tid] = (nd < NN) ? z[nd] : 0;
        sIn[tid * 68 + 64] = (nd < NN) ? t[nd] : 0.f;
    }
    __syncthreads();

    for (int i = tid; i < 64 * 16; i += 256) {
        int nd = i >> 4, c = i & 15;
        float4 v = ((const float4*)emb)[(size_t)sZ[nd] * 16 + c];
        ((float4*)(sIn + nd * 68))[c] = v;
    }
    __syncthreads();

    const int w = tid >> 5, l = tid & 31;
    const int ln0 = w * 8;

    ull acc0[8], acc1[8];
    {
        ull bb0 = pk2(sb1[l], 0.f);
        ull bb1 = pk2(sb1[l + 32], 0.f);
#pragma unroll
        for (int j = 0; j < 8; j++) { acc0[j] = bb0; acc1[j] = bb1; }
    }

#pragma unroll 8
    for (int k = 0; k < 64; k += 2) {
        ull w0p = pk2(sW1[k * 64 + l],      sW1[(k + 1) * 64 + l]);
        ull w1p = pk2(sW1[k * 64 + l + 32], sW1[(k + 1) * 64 + l + 32]);
#pragma unroll
        for (int j = 0; j < 8; j++) {
            ull vp = *(const ull*)&sIn[(ln0 + j) * 68 + k];
            acc0[j] = ffma2(vp, w0p, acc0[j]);
            acc1[j] = ffma2(vp, w1p, acc1[j]);
        }
    }
    {   // k = 64 tail (the t column): packed (v,0)*(w,w) adds to lo only
        ull w0p = pk2(sW1[64 * 64 + l],      sW1[64 * 64 + l]);
        ull w1p = pk2(sW1[64 * 64 + l + 32], sW1[64 * 64 + l + 32]);
#pragma unroll
        for (int j = 0; j < 8; j++) {
            ull vp = pk2(sIn[(ln0 + j) * 68 + 64], 0.f);
            acc0[j] = ffma2(vp, w0p, acc0[j]);
            acc1[j] = ffma2(vp, w1p, acc1[j]);
        }
    }

    __syncwarp();
#pragma unroll
    for (int j = 0; j < 8; j++) {
        float x0, x1, y0, y1;
        upk2(acc0[j], x0, x1);
        upk2(acc1[j], y0, y1);
        sIn[(ln0 + j) * 68 + l]      = frelu(x0 + x1);
        sIn[(ln0 + j) * 68 + l + 32] = frelu(y0 + y1);
    }
    __syncwarp();

    {
        ull bb0 = pk2(sb2[l], 0.f);
        ull bb1 = pk2(sb2[l + 32], 0.f);
#pragma unroll
        for (int j = 0; j < 8; j++) { acc0[j] = bb0; acc1[j] = bb1; }
    }

#pragma unroll 8
    for (int k = 0; k < 64; k += 2) {
        ull w0p = pk2(sW2[k * 64 + l],      sW2[(k + 1) * 64 + l]);
        ull w1p = pk2(sW2[k * 64 + l + 32], sW2[(k + 1) * 64 + l + 32]);
#pragma unroll
        for (int j = 0; j < 8; j++) {
            ull vp = *(const ull*)&sIn[(ln0 + j) * 68 + k];
            acc0[j] = ffma2(vp, w0p, acc0[j]);
            acc1[j] = ffma2(vp, w1p, acc1[j]);
        }
    }

#pragma unroll
    for (int j = 0; j < 8; j++) {
        int nd = base + ln0 + j;
        if (nd < NN) {
            float x0, x1, y0, y1;
            upk2(acc0[j], x0, x1);
            upk2(acc1[j], y0, y1);
            float v0 = x0 + x1, v1 = y0 + y1;
            out1[(size_t)nd * 64 + l] = v0;
            out1[(size_t)nd * 64 + l + 32] = v1;
            out2[(size_t)nd * 64 + l] = v0;
            out2[(size_t)nd * 64 + l + 32] = v1;
        }
    }
}

// ---------------------------------------------------------------------------
// Launch
// ---------------------------------------------------------------------------
extern "C" void kernel_launch(void* const* d_in, const int* in_sizes, int n_in,
                              void* d_out, int out_size)
{
    const int*   z    = (const int*)  d_in[0];
    const int*   ei   = (const int*)  d_in[1];   // [2, E]: src = ei, dst = ei + EE
    const float* ea   = (const float*)d_in[2];
    const float* t    = (const float*)d_in[3];
    const float* emb  = (const float*)d_in[4];
    const float* rw1  = (const float*)d_in[5];
    const float* rb1  = (const float*)d_in[6];
    const float* rw2  = (const float*)d_in[7];
    const float* rb2  = (const float*)d_in[8];
    const float* cw1  = (const float*)d_in[9];
    const float* cb1  = (const float*)d_in[10];
    const float* cw2  = (const float*)d_in[11];
    const float* cb2  = (const float*)d_in[12];
    float* out = (float*)d_out;

    float* hp = nullptr;
    float* ap = nullptr;
    cudaGetSymbolAddress((void**)&hp, g_h);
    cudaGetSymbolAddress((void**)&ap, g_agg);

    const int init_smem = INIT_SMEM_FLOATS * sizeof(float);
    const int mlp_smem  = MLP_SMEM_FLOATS * sizeof(float);
    cudaFuncSetAttribute(init_kernel, cudaFuncAttributeMaxDynamicSharedMemorySize, init_smem);
    cudaFuncSetAttribute(mlp_kernel,  cudaFuncAttributeMaxDynamicSharedMemorySize, mlp_smem);

    const int nblk_node = (NN + 63) / 64;
    const int nblk_edge = (HALF_E * 8) / 256;   // 25000, exact

    init_kernel<<<nblk_node, 256, init_smem>>>(z, t, emb, rw1, rb1, rw2, rb2, hp, ap);

    for (int li = 0; li < 3; li++) {
        edge_kernel<<<nblk_edge, 256>>>((const float4*)hp, (const float4*)ea,
                                        ei, ei + EE, (float4*)ap);
        const float* W1 = cw1 + li * 4096;
        const float* b1 = cb1 + li * 64;
        const float* W2 = cw2 + li * 4096;
        const float* b2 = cb2 + li * 64;
        if (li < 2) {
            mlp_kernel<<<nblk_node, 256, mlp_smem>>>(ap, hp, W1, b1, W2, b2, hp, ap, 1);
        } else {
            mlp_kernel<<<nblk_node, 256, mlp_smem>>>(ap, hp, W1, b1, W2, b2, out, nullptr, 0);
        }
    }
}

// round 8
// speedup vs baseline: 1.4486x; 1.4486x over previous
#include <cuda_runtime.h>

#define NN 100000
#define EE 1600000
#define HH 64

// Scratch (device globals; no allocation allowed)
__device__ float g_h[NN * HH];
__device__ float g_agg[NN * HH];

__device__ __forceinline__ float frelu(float x) { return x > 0.f ? x : 0.f; }

typedef unsigned long long ull;

// ---- packed f32x2 helpers (FFMA2 — only reachable via PTX) -----------------
__device__ __forceinline__ ull pk2(float lo, float hi) {
    ull r;
    asm("mov.b64 %0, {%1,%2};" : "=l"(r) : "f"(lo), "f"(hi));
    return r;
}
__device__ __forceinline__ void upk2(ull v, float& lo, float& hi) {
    asm("mov.b64 {%0,%1}, %2;" : "=f"(lo), "=f"(hi) : "l"(v));
}
__device__ __forceinline__ ull ffma2(ull a, ull b, ull c) {
    ull d;
    asm("fma.rn.f32x2 %0, %1, %2, %3;" : "=l"(d) : "l"(a), "l"(b), "l"(c));
    return d;
}

// ---------------------------------------------------------------------------
// Edge kernel (R3 shape — measured best): msg = relu(h[src] + edge_attr);
// agg[dst] += msg. 8 threads/edge, 2 float4 chunks each.
// __ldcs on the 410MB edge_attr stream (evict-first, keeps L2 for h/agg).
// __ldcg on h gathers (L2-resident, ~0 L1 hit rate -> skip L1 allocation to
// cut L1tex wavefront pressure, the binding pipe per R7 evidence).
// ---------------------------------------------------------------------------
__global__ void __launch_bounds__(256) edge_kernel(
    const float4* __restrict__ h,
    const float4* __restrict__ ea,
    const int* __restrict__ src,
    const int* __restrict__ dst,
    float4* __restrict__ agg)
{
    int t = blockIdx.x * 256 + threadIdx.x;
    int e = t >> 3;
    if (e >= EE) return;
    int c = t & 7;

    int s = __ldg(&src[e]);
    int d = __ldg(&dst[e]);

    float4 a0 = __ldcs(&ea[(size_t)e * 16 + c]);
    float4 a1 = __ldcs(&ea[(size_t)e * 16 + c + 8]);
    float4 h0 = __ldcg(&h[(size_t)s * 16 + c]);
    float4 h1 = __ldcg(&h[(size_t)s * 16 + c + 8]);

    float4 m0, m1;
    m0.x = frelu(a0.x + h0.x); m0.y = frelu(a0.y + h0.y);
    m0.z = frelu(a0.z + h0.z); m0.w = frelu(a0.w + h0.w);
    m1.x = frelu(a1.x + h1.x); m1.y = frelu(a1.y + h1.y);
    m1.z = frelu(a1.z + h1.z); m1.w = frelu(a1.w + h1.w);

    atomicAdd(&agg[(size_t)d * 16 + c], m0);
    atomicAdd(&agg[(size_t)d * 16 + c + 8], m1);
}

// ---------------------------------------------------------------------------
// Conv MLP kernel (R4-proposal, measured best): FFMA2, k-packed, no transpose.
// out = relu_opt(relu(in@W1+b1)@W2+b2) + resid
// 256 threads = 8 warps, 64 nodes/block, 8 nodes/warp. Packed (even-k, odd-k)
// accumulators; value load (in[nd][k], in[nd][k+1]) contiguous in natural
// [node][dim] layout (warp-broadcast LDS.64). Horizontal add at the end.
// ---------------------------------------------------------------------------
#define MLP_SMEM_FLOATS (4096 + 4096 + 64 + 64 + 64 * 64)
__global__ void __launch_bounds__(256) mlp_kernel(
    const float* __restrict__ in,
    const float* __restrict__ resid,
    const float* __restrict__ W1, const float* __restrict__ b1,
    const float* __restrict__ W2, const float* __restrict__ b2,
    float* __restrict__ out1, float* __restrict__ out2,
    int relu_out)
{
    extern __shared__ float sm[];
    float* sW1 = sm;              // 64*64
    float* sW2 = sm + 4096;       // 64*64
    float* sb1 = sm + 8192;       // 64
    float* sb2 = sm + 8256;       // 64
    float* sIn = sm + 8320;       // [node][64], natural layout

    const int tid = threadIdx.x;
    const int base = blockIdx.x * 64;

    for (int i = tid; i < 4096; i += 256) { sW1[i] = W1[i]; sW2[i] = W2[i]; }
    if (tid < 64) { sb1[tid] = b1[tid]; sb2[tid] = b2[tid]; }
    for (int i = tid; i < 64 * 16; i += 256) {
        int nd = i >> 4, c = i & 15;
        float4 v = make_float4(0.f, 0.f, 0.f, 0.f);
        if (base + nd < NN) v = ((const float4*)in)[(size_t)(base + nd) * 16 + c];
        ((float4*)(sIn + nd * 64))[c] = v;
    }
    __syncthreads();

    const int w = tid >> 5, l = tid & 31;
    const int ln0 = w * 8;

    ull acc0[8], acc1[8];
    {
        ull bb0 = pk2(sb1[l], 0.f);
        ull bb1 = pk2(sb1[l + 32], 0.f);
#pragma unroll
        for (int j = 0; j < 8; j++) { acc0[j] = bb0; acc1[j] = bb1; }
    }

#pragma unroll 8
    for (int k = 0; k < 64; k += 2) {
        ull w0p = pk2(sW1[k * 64 + l],      sW1[(k + 1) * 64 + l]);
        ull w1p = pk2(sW1[k * 64 + l + 32], sW1[(k + 1) * 64 + l + 32]);
#pragma unroll
        for (int j = 0; j < 8; j++) {
            ull vp = *(const ull*)&sIn[(ln0 + j) * 64 + k];
            acc0[j] = ffma2(vp, w0p, acc0[j]);
            acc1[j] = ffma2(vp, w1p, acc1[j]);
        }
    }

    __syncwarp();
#pragma unroll
    for (int j = 0; j < 8; j++) {
        float x0, x1, y0, y1;
        upk2(acc0[j], x0, x1);
        upk2(acc1[j], y0, y1);
        sIn[(ln0 + j) * 64 + l]      = frelu(x0 + x1);
        sIn[(ln0 + j) * 64 + l + 32] = frelu(y0 + y1);
    }
    __syncwarp();

    {
        ull bb0 = pk2(sb2[l], 0.f);
        ull bb1 = pk2(sb2[l + 32], 0.f);
#pragma unroll
        for (int j = 0; j < 8; j++) { acc0[j] = bb0; acc1[j] = bb1; }
    }

#pragma unroll 8
    for (int k = 0; k < 64; k += 2) {
        ull w0p = pk2(sW2[k * 64 + l],      sW2[(k + 1) * 64 + l]);
        ull w1p = pk2(sW2[k * 64 + l + 32], sW2[(k + 1) * 64 + l + 32]);
#pragma unroll
        for (int j = 0; j < 8; j++) {
            ull vp = *(const ull*)&sIn[(ln0 + j) * 64 + k];
            acc0[j] = ffma2(vp, w0p, acc0[j]);
            acc1[j] = ffma2(vp, w1p, acc1[j]);
        }
    }

#pragma unroll
    for (int j = 0; j < 8; j++) {
        int nd = base + ln0 + j;
        if (nd < NN) {
            float x0, x1, y0, y1;
            upk2(acc0[j], x0, x1);
            upk2(acc1[j], y0, y1);
            float v0 = x0 + x1, v1 = y0 + y1;
            if (relu_out) { v0 = frelu(v0); v1 = frelu(v1); }
            v0 += resid[(size_t)nd * 64 + l];
            v1 += resid[(size_t)nd * 64 + l + 32];
            out1[(size_t)nd * 64 + l] = v0;
            out1[(size_t)nd * 64 + l + 32] = v1;
            if (out2) { out2[(size_t)nd * 64 + l] = v0; out2[(size_t)nd * 64 + l + 32] = v1; }
        }
    }
}

// ---------------------------------------------------------------------------
// Init kernel (R4-proposal): h0 = relu(concat(emb[z],t)@rw1+rb1)@rw2+rb2
// Input dim 65: emb in [nd][0..63] (stride 68), t at [nd][64]. Writes h0 to
// both g_h and g_agg.
// ---------------------------------------------------------------------------
#define INIT_SMEM_FLOATS (65 * 64 + 4096 + 64 + 64 + 64 * 68)
__global__ void __launch_bounds__(256) init_kernel(
    const int* __restrict__ z,
    const float* __restrict__ t,
    const float* __restrict__ emb,
    const float* __restrict__ W1, const float* __restrict__ b1,
    const float* __restrict__ W2, const float* __restrict__ b2,
    float* __restrict__ out1, float* __restrict__ out2)
{
    extern __shared__ float sm[];
    float* sW1 = sm;                    // 65*64 = 4160
    float* sW2 = sm + 4160;             // 64*64
    float* sb1 = sm + 8256;             // 64
    float* sb2 = sm + 8320;             // 64
    float* sIn = sm + 8384;             // [node][68] (65 used)
    __shared__ int sZ[64];

    const int tid = threadIdx.x;
    const int base = blockIdx.x * 64;

    for (int i = tid; i < 4160; i += 256) sW1[i] = W1[i];
    for (int i = tid; i < 4096; i += 256) sW2[i] = W2[i];
    if (tid < 64) {
        sb1[tid] = b1[tid]; sb2[tid] = b2[tid];
        int nd = base + tid;
        sZ[tid] = (nd < NN) ? z[nd] : 0;
        sIn[tid * 68 + 64] = (nd < NN) ? t[nd] : 0.f;
    }
    __syncthreads();

    for (int i = tid; i < 64 * 16; i += 256) {
        int nd = i >> 4, c = i & 15;
        float4 v = ((const float4*)emb)[(size_t)sZ[nd] * 16 + c];
        ((float4*)(sIn + nd * 68))[c] = v;
    }
    __syncthreads();

    const int w = tid >> 5, l = tid & 31;
    const int ln0 = w * 8;

    ull acc0[8], acc1[8];
    {
        ull bb0 = pk2(sb1[l], 0.f);
        ull bb1 = pk2(sb1[l + 32], 0.f);
#pragma unroll
        for (int j = 0; j < 8; j++) { acc0[j] = bb0; acc1[j] = bb1; }
    }

#pragma unroll 8
    for (int k = 0; k < 64; k += 2) {
        ull w0p = pk2(sW1[k * 64 + l],      sW1[(k + 1) * 64 + l]);
        ull w1p = pk2(sW1[k * 64 + l + 32], sW1[(k + 1) * 64 + l + 32]);
#pragma unroll
        for (int j = 0; j < 8; j++) {
            ull vp = *(const ull*)&sIn[(ln0 + j) * 68 + k];
            acc0[j] = ffma2(vp, w0p, acc0[j]);
            acc1[j] = ffma2(vp, w1p, acc1[j]);
        }
    }
    {   // k = 64 tail (the t column): packed (v,0)*(w,w) adds to lo only
        ull w0p = pk2(sW1[64 * 64 + l],      sW1[64 * 64 + l]);
        ull w1p = pk2(sW1[64 * 64 + l + 32], sW1[64 * 64 + l + 32]);
#pragma unroll
        for (int j = 0; j < 8; j++) {
            ull vp = pk2(sIn[(ln0 + j) * 68 + 64], 0.f);
            acc0[j] = ffma2(vp, w0p, acc0[j]);
            acc1[j] = ffma2(vp, w1p, acc1[j]);
        }
    }

    __syncwarp();
#pragma unroll
    for (int j = 0; j < 8; j++) {
        float x0, x1, y0, y1;
        upk2(acc0[j], x0, x1);
        upk2(acc1[j], y0, y1);
        sIn[(ln0 + j) * 68 + l]      = frelu(x0 + x1);
        sIn[(ln0 + j) * 68 + l + 32] = frelu(y0 + y1);
    }
    __syncwarp();

    {
        ull bb0 = pk2(sb2[l], 0.f);
        ull bb1 = pk2(sb2[l + 32], 0.f);
#pragma unroll
        for (int j = 0; j < 8; j++) { acc0[j] = bb0; acc1[j] = bb1; }
    }

#pragma unroll 8
    for (int k = 0; k < 64; k += 2) {
        ull w0p = pk2(sW2[k * 64 + l],      sW2[(k + 1) * 64 + l]);
        ull w1p = pk2(sW2[k * 64 + l + 32], sW2[(k + 1) * 64 + l + 32]);
#pragma unroll
        for (int j = 0; j < 8; j++) {
            ull vp = *(const ull*)&sIn[(ln0 + j) * 68 + k];
            acc0[j] = ffma2(vp, w0p, acc0[j]);
            acc1[j] = ffma2(vp, w1p, acc1[j]);
        }
    }

#pragma unroll
    for (int j = 0; j < 8; j++) {
        int nd = base + ln0 + j;
        if (nd < NN) {
            float x0, x1, y0, y1;
            upk2(acc0[j], x0, x1);
            upk2(acc1[j], y0, y1);
            float v0 = x0 + x1, v1 = y0 + y1;
            out1[(size_t)nd * 64 + l] = v0;
            out1[(size_t)nd * 64 + l + 32] = v1;
            out2[(size_t)nd * 64 + l] = v0;
            out2[(size_t)nd * 64 + l + 32] = v1;
        }
    }
}

// ---------------------------------------------------------------------------
// Launch
// ---------------------------------------------------------------------------
extern "C" void kernel_launch(void* const* d_in, const int* in_sizes, int n_in,
                              void* d_out, int out_size)
{
    const int*   z    = (const int*)  d_in[0];
    const int*   ei   = (const int*)  d_in[1];   // [2, E]: src = ei, dst = ei + EE
    const float* ea   = (const float*)d_in[2];
    const float* t    = (const float*)d_in[3];
    const float* emb  = (const float*)d_in[4];
    const float* rw1  = (const float*)d_in[5];
    const float* rb1  = (const float*)d_in[6];
    const float* rw2  = (const float*)d_in[7];
    const float* rb2  = (const float*)d_in[8];
    const float* cw1  = (const float*)d_in[9];
    const float* cb1  = (const float*)d_in[10];
    const float* cw2  = (const float*)d_in[11];
    const float* cb2  = (const float*)d_in[12];
    float* out = (float*)d_out;

    float* hp = nullptr;
    float* ap = nullptr;
    cudaGetSymbolAddress((void**)&hp, g_h);
    cudaGetSymbolAddress((void**)&ap, g_agg);

    const int init_smem = INIT_SMEM_FLOATS * sizeof(float);
    const int mlp_smem  = MLP_SMEM_FLOATS * sizeof(float);
    cudaFuncSetAttribute(init_kernel, cudaFuncAttributeMaxDynamicSharedMemorySize, init_smem);
    cudaFuncSetAttribute(mlp_kernel,  cudaFuncAttributeMaxDynamicSharedMemorySize, mlp_smem);

    const int nblk_node = (NN + 63) / 64;
    const int nblk_edge = (EE * 8 + 255) / 256;

    init_kernel<<<nblk_node, 256, init_smem>>>(z, t, emb, rw1, rb1, rw2, rb2, hp, ap);

    for (int li = 0; li < 3; li++) {
        edge_kernel<<<nblk_edge, 256>>>((const float4*)hp, (const float4*)ea,
                                        ei, ei + EE, (float4*)ap);
        const float* W1 = cw1 + li * 4096;
        const float* b1 = cb1 + li * 64;
        const float* W2 = cw2 + li * 4096;
        const float* b2 = cb2 + li * 64;
        if (li < 2) {
            mlp_kernel<<<nblk_node, 256, mlp_smem>>>(ap, hp, W1, b1, W2, b2, hp, ap, 1);
        } else {
            mlp_kernel<<<nblk_node, 256, mlp_smem>>>(ap, hp, W1, b1, W2, b2, out, nullptr, 0);
        }
    }
}